// round 1
// baseline (speedup 1.0000x reference)
#include <cuda_runtime.h>
#include <math.h>

#define SEQ   256
#define BATCH 32
#define REC   16
#define EMB   32
#define VOCAB 32000
#define NROWS (SEQ*BATCH)   // 8192
#define CHUNK 256
#define NCHUNK (VOCAB/CHUNK) // 125

// Scratch (no allocation allowed in kernel_launch)
__device__ float g_ih[NROWS*REC];      // precomputed input-to-hidden (x_t @ U^T + b1)
__device__ float g_hidden[NROWS*REC];  // hidden[t] = state BEFORE step t (per reference)
__device__ float g_lse[NROWS];         // per-row log-sum-exp

// ---------- packed f32x2 helpers (Blackwell FFMA2) ----------
__device__ __forceinline__ unsigned long long pack2(float x) {
    unsigned long long r;
    asm("mov.b64 %0, {%1, %1};" : "=l"(r) : "f"(x));
    return r;
}
__device__ __forceinline__ void fma2(unsigned long long& d, unsigned long long a,
                                     unsigned long long b) {
    asm("fma.rn.f32x2 %0, %1, %2, %0;" : "+l"(d) : "l"(a), "l"(b));
}
__device__ __forceinline__ unsigned long long add2(unsigned long long a,
                                                   unsigned long long b) {
    unsigned long long d;
    asm("add.rn.f32x2 %0, %1, %2;" : "=l"(d) : "l"(a), "l"(b));
    return d;
}
__device__ __forceinline__ float2 unpack2(unsigned long long v) {
    float2 r;
    asm("mov.b64 {%0, %1}, %2;" : "=f"(r.x), "=f"(r.y) : "l"(v));
    return r;
}

// ---------- Kernel 1: i_h[t][b][r] = emb[input[t][b]] . U[r] + b1[r] ----------
// Fully parallel (no dependence on recurrent state).
__global__ void ih_kernel(const int* __restrict__ inp, const float* __restrict__ emb,
                          const float* __restrict__ U, const float* __restrict__ b1) {
    __shared__ float Us[REC*EMB];
    int tid = threadIdx.x;
    for (int i = tid; i < REC*EMB; i += 256) Us[i] = U[i];
    __syncthreads();
    int row = blockIdx.x * 16 + (tid >> 4);  // (t,b) flattened
    int r   = tid & 15;
    int idx = inp[row];
    const float* e = emb + (size_t)idx * EMB;
    float acc = b1[r];
#pragma unroll
    for (int k = 0; k < EMB; k++) acc += e[k] * Us[r*EMB + k];
    g_ih[row*REC + r] = acc;
}

// ---------- Kernel 2: serial recurrence (1 block, 512 threads = 32 b x 16 r) ----------
// hidden[0] = h0; for t: h = tanh(ih[t] + h@W^T + b2); hidden[t+1] = h.
// (Reference stores h BEFORE update, so hidden[t] is pre-step state; ih[255] unused.)
__global__ void rnn_kernel(const float* __restrict__ W, const float* __restrict__ b2,
                           const float* __restrict__ h0v) {
    __shared__ float hs[BATCH*REC];
    int tid = threadIdx.x;          // 0..511
    int b = tid >> 4, r = tid & 15;
    float w[REC];
#pragma unroll
    for (int k = 0; k < REC; k++) w[k] = W[r*REC + k];
    float bias = b2[r];
    float h = h0v[r];
    hs[tid] = h;
    g_hidden[tid] = h;              // t = 0
    __syncthreads();
    float ihv = g_ih[tid];          // prefetch t=0
    for (int t = 0; t < SEQ-1; t++) {
        float ihn = 0.f;
        if (t < SEQ-2) ihn = g_ih[(t+1)*(BATCH*REC) + tid];  // prefetch next
        float acc = ihv + bias;
#pragma unroll
        for (int k = 0; k < REC; k++) acc += hs[b*REC + k] * w[k];
        float hn = tanhf(acc);
        __syncthreads();
        hs[tid] = hn;
        g_hidden[(size_t)(t+1)*(BATCH*REC) + tid] = hn;
        __syncthreads();
        ihv = ihn;
    }
}

// ---------- GEMM core: 16 rows/block, 256-vocab chunks, f32x2 math ----------
// PASS 0: accumulate sumexp per row -> g_lse (no max needed: |logit| <= 4).
// PASS 1: recompute logits, write logit - lse via STG.128.
template <int PASS>
__global__ __launch_bounds__(256, 2)
void gemm_kernel(const float* __restrict__ Vm, float* __restrict__ out) {
    __shared__ __align__(16) float vbuf[REC][CHUNK];  // V chunk, transposed [k][v]
    __shared__ float red[16*64];                      // pass-0 reduction
    int tid = threadIdx.x;
    int vt = tid & 63;          // vocab-thread: 4 consecutive vocab each
    int rg = tid >> 6;          // row group: 4 rows each
    int rowbase = blockIdx.x * 16 + rg * 4;

    // Resident hidden for 4 rows (64 regs)
    float h[4][REC];
#pragma unroll
    for (int i = 0; i < 4; i++) {
        const float4* hp4 = (const float4*)(g_hidden + (size_t)(rowbase + i) * REC);
        float4 p0 = hp4[0], p1 = hp4[1], p2 = hp4[2], p3 = hp4[3];
        h[i][0]=p0.x;  h[i][1]=p0.y;  h[i][2]=p0.z;  h[i][3]=p0.w;
        h[i][4]=p1.x;  h[i][5]=p1.y;  h[i][6]=p1.z;  h[i][7]=p1.w;
        h[i][8]=p2.x;  h[i][9]=p2.y;  h[i][10]=p2.z; h[i][11]=p2.w;
        h[i][12]=p3.x; h[i][13]=p3.y; h[i][14]=p3.z; h[i][15]=p3.w;
    }

    unsigned long long nl[4];
    float sum[4] = {0.f, 0.f, 0.f, 0.f};
    if (PASS == 1) {
#pragma unroll
        for (int i = 0; i < 4; i++) nl[i] = pack2(-g_lse[rowbase + i]);
    }

    for (int c = 0; c < NCHUNK; c++) {
        // Stage: thread tid loads V row (c*256+tid), stores transposed to smem
        const float4* vr = (const float4*)(Vm + (size_t)(c*CHUNK + tid) * REC);
        float4 a0 = vr[0], a1 = vr[1], a2 = vr[2], a3 = vr[3];
        __syncthreads();
        vbuf[0][tid]=a0.x;  vbuf[1][tid]=a0.y;  vbuf[2][tid]=a0.z;  vbuf[3][tid]=a0.w;
        vbuf[4][tid]=a1.x;  vbuf[5][tid]=a1.y;  vbuf[6][tid]=a1.z;  vbuf[7][tid]=a1.w;
        vbuf[8][tid]=a2.x;  vbuf[9][tid]=a2.y;  vbuf[10][tid]=a2.z; vbuf[11][tid]=a2.w;
        vbuf[12][tid]=a3.x; vbuf[13][tid]=a3.y; vbuf[14][tid]=a3.z; vbuf[15][tid]=a3.w;
        __syncthreads();

        unsigned long long acc[4][2];
#pragma unroll
        for (int i = 0; i < 4; i++) { acc[i][0] = 0ULL; acc[i][1] = 0ULL; }

#pragma unroll
        for (int k = 0; k < REC; k++) {
            // 4 consecutive vocab values at this k: two f32x2 operands in one LDS.128
            ulonglong2 vv = *(const ulonglong2*)&vbuf[k][vt * 4];
#pragma unroll
            for (int i = 0; i < 4; i++) {
                unsigned long long hp = pack2(h[i][k]);
                fma2(acc[i][0], hp, vv.x);
                fma2(acc[i][1], hp, vv.y);
            }
        }

        if (PASS == 0) {
#pragma unroll
            for (int i = 0; i < 4; i++) {
                float2 p0 = unpack2(acc[i][0]);
                float2 p1 = unpack2(acc[i][1]);
                sum[i] += __expf(p0.x) + __expf(p0.y) + __expf(p1.x) + __expf(p1.y);
            }
        } else {
#pragma unroll
            for (int i = 0; i < 4; i++) {
                ulonglong2 o;
                o.x = add2(acc[i][0], nl[i]);
                o.y = add2(acc[i][1], nl[i]);
                *(ulonglong2*)(out + (size_t)(rowbase + i) * VOCAB + c*CHUNK + vt*4) = o;
            }
        }
    }

    if (PASS == 0) {
        __syncthreads();
#pragma unroll
        for (int i = 0; i < 4; i++) red[(rg*4 + i)*64 + vt] = sum[i];
        __syncthreads();
        if (tid < 16) {
            float s = 0.f;
            for (int j = 0; j < 64; j++) s += red[tid*64 + j];
            g_lse[blockIdx.x*16 + tid] = logf(s);
        }
    }
}

extern "C" void kernel_launch(void* const* d_in, const int* in_sizes, int n_in,
                              void* d_out, int out_size) {
    const int*   inp = (const int*)d_in[0];
    const float* emb = (const float*)d_in[1];
    const float* U   = (const float*)d_in[2];
    const float* W   = (const float*)d_in[3];
    const float* Vm  = (const float*)d_in[4];
    const float* b1  = (const float*)d_in[5];
    const float* b2  = (const float*)d_in[6];
    const float* h0  = (const float*)d_in[7];
    float* out = (float*)d_out;

    ih_kernel<<<NROWS/16, 256>>>(inp, emb, U, b1);
    rnn_kernel<<<1, BATCH*REC>>>(W, b2, h0);
    gemm_kernel<0><<<NROWS/16, 256>>>(Vm, out);
    gemm_kernel<1><<<NROWS/16, 256>>>(Vm, out);
}

// round 2
// speedup vs baseline: 1.3043x; 1.3043x over previous
#include <cuda_runtime.h>
#include <math.h>

#define SEQ   256
#define BATCH 32
#define REC   16
#define EMB   32
#define VOCAB 32000
#define NROWS (SEQ*BATCH)    // 8192
#define CHUNK 256
#define NCHUNK (VOCAB/CHUNK) // 125

// Scratch (no allocation allowed in kernel_launch)
__device__ float g_ih[NROWS*REC];        // precomputed x_t @ U^T + b1
__device__ float g_hidden[NROWS*REC];    // hidden[t] = state BEFORE step t
__device__ float g_lse[NROWS];           // per-row log-sum-exp
__device__ __align__(16) float g_vt[REC][VOCAB];  // V transposed [k][v], 2 MB

// ---------- packed f32x2 helpers (Blackwell FFMA2) ----------
__device__ __forceinline__ unsigned long long pack2(float x) {
    unsigned long long r;
    asm("mov.b64 %0, {%1, %1};" : "=l"(r) : "f"(x));
    return r;
}
__device__ __forceinline__ void fma2(unsigned long long& d, unsigned long long a,
                                     unsigned long long b) {
    asm("fma.rn.f32x2 %0, %1, %2, %0;" : "+l"(d) : "l"(a), "l"(b));
}
__device__ __forceinline__ unsigned long long add2(unsigned long long a,
                                                   unsigned long long b) {
    unsigned long long d;
    asm("add.rn.f32x2 %0, %1, %2;" : "=l"(d) : "l"(a), "l"(b));
    return d;
}
__device__ __forceinline__ float2 unpack2(unsigned long long v) {
    float2 r;
    asm("mov.b64 {%0, %1}, %2;" : "=f"(r.x), "=f"(r.y) : "l"(v));
    return r;
}

// ---------- Kernel 0: transpose V [VOCAB][REC] -> g_vt[REC][VOCAB] ----------
__global__ void vt_kernel(const float* __restrict__ Vm) {
    int v = blockIdx.x * 256 + threadIdx.x;   // one vocab row per thread
    const float4* vr = (const float4*)(Vm + (size_t)v * REC);
    float4 a0 = vr[0], a1 = vr[1], a2 = vr[2], a3 = vr[3];
    g_vt[0][v]=a0.x;  g_vt[1][v]=a0.y;  g_vt[2][v]=a0.z;  g_vt[3][v]=a0.w;
    g_vt[4][v]=a1.x;  g_vt[5][v]=a1.y;  g_vt[6][v]=a1.z;  g_vt[7][v]=a1.w;
    g_vt[8][v]=a2.x;  g_vt[9][v]=a2.y;  g_vt[10][v]=a2.z; g_vt[11][v]=a2.w;
    g_vt[12][v]=a3.x; g_vt[13][v]=a3.y; g_vt[14][v]=a3.z; g_vt[15][v]=a3.w;
}

// ---------- Kernel 1: i_h = emb[input] @ U^T + b1 (fully parallel) ----------
__global__ void ih_kernel(const int* __restrict__ inp, const float* __restrict__ emb,
                          const float* __restrict__ U, const float* __restrict__ b1) {
    __shared__ float Us[REC*EMB];
    int tid = threadIdx.x;
    for (int i = tid; i < REC*EMB; i += 256) Us[i] = U[i];
    __syncthreads();
    int row = blockIdx.x * 16 + (tid >> 4);
    int r   = tid & 15;
    int idx = inp[row];
    const float* e = emb + (size_t)idx * EMB;
    float acc = b1[r];
#pragma unroll
    for (int k = 0; k < EMB; k++) acc += e[k] * Us[r*EMB + k];
    g_ih[row*REC + r] = acc;
}

// ---------- Kernel 2: serial recurrence (1 block, 512 thr = 32 b x 16 r) ----------
__global__ void rnn_kernel(const float* __restrict__ W, const float* __restrict__ b2,
                           const float* __restrict__ h0v) {
    __shared__ __align__(16) float hs[BATCH*REC];
    int tid = threadIdx.x;
    int b = tid >> 4, r = tid & 15;
    float w[REC];
#pragma unroll
    for (int k = 0; k < REC; k++) w[k] = W[r*REC + k];
    float bias = b2[r];
    float h = h0v[r];
    hs[tid] = h;
    g_hidden[tid] = h;
    __syncthreads();
    float ihv = g_ih[tid];
    for (int t = 0; t < SEQ-1; t++) {
        float ihn = 0.f;
        if (t < SEQ-2) ihn = g_ih[(t+1)*(BATCH*REC) + tid];
        const float4* hp = (const float4*)(hs + b*REC);
        float4 p0 = hp[0], p1 = hp[1], p2 = hp[2], p3 = hp[3];
        float acc = ihv + bias;
        acc += p0.x*w[0]  + p0.y*w[1]  + p0.z*w[2]  + p0.w*w[3];
        acc += p1.x*w[4]  + p1.y*w[5]  + p1.z*w[6]  + p1.w*w[7];
        acc += p2.x*w[8]  + p2.y*w[9]  + p2.z*w[10] + p2.w*w[11];
        acc += p3.x*w[12] + p3.y*w[13] + p3.z*w[14] + p3.w*w[15];
        float hn = tanhf(acc);
        __syncthreads();
        hs[tid] = hn;
        g_hidden[(size_t)(t+1)*(BATCH*REC) + tid] = hn;
        __syncthreads();
        ihv = ihn;
    }
}

// ---------- GEMM core: 16 rows/block, 256-vocab chunks, double-buffered ----------
// PASS 0: per-row sumexp -> g_lse (no max subtraction: |logit| <= 4).
// PASS 1: recompute logits, write logit - lse via STG.128.
template <int PASS>
__global__ __launch_bounds__(256, 2)
void gemm_kernel(float* __restrict__ out) {
    __shared__ __align__(16) float vbuf[2][REC][CHUNK];  // 32 KB ping-pong
    __shared__ float red[16*64];
    int tid = threadIdx.x;
    int vt = tid & 63;            // vocab-thread: 4 consecutive vocab
    int rg = tid >> 6;            // row group: 4 rows
    int rowbase = blockIdx.x * 16 + rg * 4;

    // Staging role: thread stages 4 k-rows (k = rg*4+j), 16B of each
    int scol = vt * 4;

    // Resident hidden for 4 rows (64 regs)
    float h[4][REC];
#pragma unroll
    for (int i = 0; i < 4; i++) {
        const float4* hp4 = (const float4*)(g_hidden + (size_t)(rowbase + i) * REC);
        float4 p0 = hp4[0], p1 = hp4[1], p2 = hp4[2], p3 = hp4[3];
        h[i][0]=p0.x;  h[i][1]=p0.y;  h[i][2]=p0.z;  h[i][3]=p0.w;
        h[i][4]=p1.x;  h[i][5]=p1.y;  h[i][6]=p1.z;  h[i][7]=p1.w;
        h[i][8]=p2.x;  h[i][9]=p2.y;  h[i][10]=p2.z; h[i][11]=p2.w;
        h[i][12]=p3.x; h[i][13]=p3.y; h[i][14]=p3.z; h[i][15]=p3.w;
    }

    unsigned long long nl[4];
    float sum[4] = {0.f, 0.f, 0.f, 0.f};
    if (PASS == 1) {
#pragma unroll
        for (int i = 0; i < 4; i++) nl[i] = pack2(-g_lse[rowbase + i]);
    }

    // Prologue: load chunk 0 staging regs
    float4 s[4];
#pragma unroll
    for (int j = 0; j < 4; j++)
        s[j] = *(const float4*)&g_vt[rg*4 + j][scol];

    int p = 0;
    for (int c = 0; c < NCHUNK; c++) {
        // Store staged chunk c; safe vs reads of vbuf[p] at iter c-2 (bar at c-1).
#pragma unroll
        for (int j = 0; j < 4; j++)
            *(float4*)&vbuf[p][rg*4 + j][scol] = s[j];
        __syncthreads();

        // Prefetch chunk c+1 (latency overlaps compute below)
        if (c + 1 < NCHUNK) {
            int nbase = (c + 1) * CHUNK + scol;
#pragma unroll
            for (int j = 0; j < 4; j++)
                s[j] = *(const float4*)&g_vt[rg*4 + j][nbase];
        }

        unsigned long long acc[4][2];
#pragma unroll
        for (int i = 0; i < 4; i++) { acc[i][0] = 0ULL; acc[i][1] = 0ULL; }

#pragma unroll
        for (int k = 0; k < REC; k++) {
            ulonglong2 vv = *(const ulonglong2*)&vbuf[p][k][vt * 4];
#pragma unroll
            for (int i = 0; i < 4; i++) {
                unsigned long long hp = pack2(h[i][k]);
                fma2(acc[i][0], hp, vv.x);
                fma2(acc[i][1], hp, vv.y);
            }
        }

        if (PASS == 0) {
#pragma unroll
            for (int i = 0; i < 4; i++) {
                float2 p0 = unpack2(acc[i][0]);
                float2 p1 = unpack2(acc[i][1]);
                sum[i] += __expf(p0.x) + __expf(p0.y) + __expf(p1.x) + __expf(p1.y);
            }
        } else {
#pragma unroll
            for (int i = 0; i < 4; i++) {
                ulonglong2 o;
                o.x = add2(acc[i][0], nl[i]);
                o.y = add2(acc[i][1], nl[i]);
                *(ulonglong2*)(out + (size_t)(rowbase + i) * VOCAB + c*CHUNK + vt*4) = o;
            }
        }
        p ^= 1;
    }

    if (PASS == 0) {
        __syncthreads();
#pragma unroll
        for (int i = 0; i < 4; i++) red[(rg*4 + i)*64 + vt] = sum[i];
        __syncthreads();
        if (tid < 16) {
            float sA = 0.f;
#pragma unroll 8
            for (int j = 0; j < 64; j++) sA += red[tid*64 + j];
            g_lse[blockIdx.x*16 + tid] = logf(sA);
        }
    }
}

extern "C" void kernel_launch(void* const* d_in, const int* in_sizes, int n_in,
                              void* d_out, int out_size) {
    const int*   inp = (const int*)d_in[0];
    const float* emb = (const float*)d_in[1];
    const float* U   = (const float*)d_in[2];
    const float* W   = (const float*)d_in[3];
    const float* Vm  = (const float*)d_in[4];
    const float* b1  = (const float*)d_in[5];
    const float* b2  = (const float*)d_in[6];
    const float* h0  = (const float*)d_in[7];
    float* out = (float*)d_out;

    vt_kernel<<<VOCAB/256, 256>>>(Vm);
    ih_kernel<<<NROWS/16, 256>>>(inp, emb, U, b1);
    rnn_kernel<<<1, BATCH*REC>>>(W, b2, h0);
    gemm_kernel<0><<<NROWS/16, 256>>>(out);
    gemm_kernel<1><<<NROWS/16, 256>>>(out);
}